// round 1
// baseline (speedup 1.0000x reference)
#include <cuda_runtime.h>

// OuterProductNetwork: out[b,n] = sum_{i,o} x[b,row(n),i] * K[o,n,i] * x[b,col(n),o]
// B=8192, F=32, D=64, NPAIR=496. Inputs: d_in[0]=x (f32 [8192,32,64]),
// d_in[1]=kernel (f32 [64,496,64]). Output f32 [8192,496].

#define BATCH   8192
#define NF      32
#define D       64
#define NPAIR   496
#define KOSTRIDE (NPAIR * D)   // stride of o index in kernel tensor (31744)
#define BT      256            // batch rows per CTA
#define KT_STRIDE 68           // padded smem row stride (floats); 68*4=272=17*16 -> 16B aligned rows

// ---- packed f32x2 helpers (Blackwell FFMA2 is only reachable via PTX) ----
__device__ __forceinline__ unsigned long long fma2(unsigned long long a,
                                                   unsigned long long b,
                                                   unsigned long long c) {
    unsigned long long d;
    asm("fma.rn.f32x2 %0, %1, %2, %3;" : "=l"(d) : "l"(a), "l"(b), "l"(c));
    return d;
}
__device__ __forceinline__ unsigned long long pack2(float lo, float hi) {
    unsigned long long d;
    asm("mov.b64 %0, {%1, %2};" : "=l"(d) : "f"(lo), "f"(hi));
    return d;
}
__device__ __forceinline__ float2 unpack2(unsigned long long v) {
    float2 f;
    asm("mov.b64 {%0, %1}, %2;" : "=f"(f.x), "=f"(f.y) : "l"(v));
    return f;
}

__global__ void __launch_bounds__(BT, 2)
opn_f32x2_kernel(const float* __restrict__ x,
                 const float* __restrict__ kern,
                 float* __restrict__ out) {
    // K_n transposed into smem: Kt[i][o] = kern[o, n, i]. Row i is 64 floats of o,
    // read as 16B-aligned LDS.128 broadcasts (all lanes same address -> conflict free).
    __shared__ float Kt[D * KT_STRIDE];   // 17408 B

    const int n = blockIdx.y;
    const int t = threadIdx.x;
    const int b = blockIdx.x * BT + t;

    // pair n -> (r, c) of triu_indices(32, k=1), row-major
    int r = 0, n0 = n;
    while (n0 >= 31 - r) { n0 -= 31 - r; ++r; }
    const int c = r + 1 + n0;

    // Stage K transposed. Global reads coalesced (i contiguous within an o-row).
    {
        const float* kb = kern + n * D;
        #pragma unroll
        for (int k = 0; k < (D * D) / BT; ++k) {
            int e = k * BT + t;
            int o = e >> 6;
            int i = e & 63;
            Kt[i * KT_STRIDE + o] = kb[o * KOSTRIDE + i];
        }
    }
    __syncthreads();

    const float* px = x + (b * NF + r) * D;   // p = x[b, r, :]
    const float* qx = x + (b * NF + c) * D;   // q = x[b, c, :]

    // y[j] accumulates (y_{2j}, y_{2j+1}) over o, as packed f32x2.
    unsigned long long y[D / 2];
    #pragma unroll
    for (int j = 0; j < D / 2; ++j) y[j] = 0ULL;

    const float4* px4 = reinterpret_cast<const float4*>(px);

    // Main loop over i: y_o += K[o,i] * p_i for all o (64 x f32 = 32 x f32x2 per i).
    #pragma unroll 4
    for (int i4 = 0; i4 < D / 4; ++i4) {
        const float4 p4 = __ldg(px4 + i4);
        const float pv[4] = {p4.x, p4.y, p4.z, p4.w};
        #pragma unroll
        for (int u = 0; u < 4; ++u) {
            const int i = i4 * 4 + u;
            const unsigned long long pp = pack2(pv[u], pv[u]);
            const ulonglong2* krow =
                reinterpret_cast<const ulonglong2*>(Kt + i * KT_STRIDE);
            #pragma unroll
            for (int j = 0; j < 16; ++j) {
                const ulonglong2 k2 = krow[j];   // LDS.128 broadcast
                y[2 * j]     = fma2(k2.x, pp, y[2 * j]);
                y[2 * j + 1] = fma2(k2.y, pp, y[2 * j + 1]);
            }
        }
    }

    // Epilogue: out = sum_o y_o * q_o. Two independent FMA2 chains.
    const ulonglong2* q2p = reinterpret_cast<const ulonglong2*>(qx);
    unsigned long long acc0 = 0ULL, acc1 = 0ULL;
    #pragma unroll
    for (int j = 0; j < 16; ++j) {
        const ulonglong2 qq = q2p[j];            // LDG.128
        acc0 = fma2(y[2 * j],     qq.x, acc0);
        acc1 = fma2(y[2 * j + 1], qq.y, acc1);
    }
    const float2 a0 = unpack2(acc0);
    const float2 a1 = unpack2(acc1);
    out[b * NPAIR + n] = (a0.x + a0.y) + (a1.x + a1.y);
}

extern "C" void kernel_launch(void* const* d_in, const int* in_sizes, int n_in,
                              void* d_out, int out_size) {
    (void)in_sizes; (void)n_in; (void)out_size;
    const float* x    = (const float*)d_in[0];
    const float* kern = (const float*)d_in[1];
    float* out        = (float*)d_out;

    dim3 grid(BATCH / BT, NPAIR, 1);
    opn_f32x2_kernel<<<grid, BT>>>(x, kern, out);
}

// round 10
// speedup vs baseline: 1.5284x; 1.5284x over previous
#include <cuda_runtime.h>

// OuterProductNetwork: out[b,n] = sum_{i,o} x[b,row(n),i] * K[o,n,i] * x[b,col(n),o]
// B=8192, F=32, D=64, NPAIR=496. d_in[0]=x f32 [8192,32,64], d_in[1]=kernel f32 [64,496,64].
// GEMM-tiled: per CTA, one pair n and 128 batch rows. Y = P @ K_n^T computed with
// 8b x 8o register tiles (f32x2-packed over o), epilogue dot with q + warp reduce.

#define BATCH   8192
#define NF      32
#define D       64
#define NPAIR   496
#define KOSTRIDE (NPAIR * D)     // 31744
#define BTILE   128              // batch rows per CTA
#define NTHR    128
#define KT_S    68               // Kt row stride (floats), 16B-aligned rows
#define PT_S    132              // Pt row stride (floats), 16B-aligned rows

__device__ __forceinline__ unsigned long long fma2(unsigned long long a,
                                                   unsigned long long b,
                                                   unsigned long long c) {
    unsigned long long d;
    asm("fma.rn.f32x2 %0, %1, %2, %3;" : "=l"(d) : "l"(a), "l"(b), "l"(c));
    return d;
}
__device__ __forceinline__ unsigned long long pack2(float lo, float hi) {
    unsigned long long d;
    asm("mov.b64 %0, {%1, %2};" : "=l"(d) : "f"(lo), "f"(hi));
    return d;
}
__device__ __forceinline__ float2 unpack2(unsigned long long v) {
    float2 f;
    asm("mov.b64 {%0, %1}, %2;" : "=f"(f.x), "=f"(f.y) : "l"(v));
    return f;
}

__global__ void __launch_bounds__(NTHR, 4)
opn_tile_kernel(const float* __restrict__ x,
                const float* __restrict__ kern,
                float* __restrict__ out) {
    __shared__ float Kt[D * KT_S];       // Kt[i*KT_S + o] = K[o,n,i]   (17.4 KB)
    __shared__ float Pt[D * PT_S];       // Pt[i*PT_S + b] = x[b0+b, r, i] (33.8 KB)

    const int n  = blockIdx.y;
    const int b0 = blockIdx.x * BTILE;
    const int t  = threadIdx.x;

    // pair n -> (r, c), row-major triu_indices(32, k=1)
    int r = 0, n0 = n;
    while (n0 >= 31 - r) { n0 -= 31 - r; ++r; }
    const int c = r + 1 + n0;

    // ---- stage K transposed: 4096 elems, 32 per thread, coalesced global reads
    {
        const float* kb = kern + n * D;
        #pragma unroll
        for (int k = 0; k < (D * D) / NTHR; ++k) {
            int e = k * NTHR + t;
            int o = e >> 6;
            int i = e & 63;
            Kt[i * KT_S + o] = kb[o * KOSTRIDE + i];
        }
    }
    // ---- stage P transposed: thread t owns batch row b0+t
    {
        const float4* prow = reinterpret_cast<const float4*>(x + ((b0 + t) * NF + r) * D);
        #pragma unroll
        for (int i4 = 0; i4 < D / 4; ++i4) {
            float4 f4 = prow[i4];
            int i = i4 * 4;
            Pt[(i + 0) * PT_S + t] = f4.x;
            Pt[(i + 1) * PT_S + t] = f4.y;
            Pt[(i + 2) * PT_S + t] = f4.z;
            Pt[(i + 3) * PT_S + t] = f4.w;
        }
    }
    __syncthreads();

    const int o_t = t & 7;    // thread's o block: o = o_t*8 .. o_t*8+7
    const int b_t = t >> 3;   // thread's b block: b = b_t*8 .. b_t*8+7

    // y[m][jo]: packed (o-pair) accumulators for 8 batch rows x 8 o values
    unsigned long long y[8][4];
    #pragma unroll
    for (int m = 0; m < 8; ++m)
        #pragma unroll
        for (int j = 0; j < 4; ++j) y[m][j] = 0ULL;

    #pragma unroll 8
    for (int i = 0; i < D; ++i) {
        const ulonglong2* kr =
            reinterpret_cast<const ulonglong2*>(Kt + i * KT_S + o_t * 8);
        const ulonglong2 ka = kr[0];       // (K[o0],K[o0+1]),(K[o0+2],K[o0+3])
        const ulonglong2 kb2 = kr[1];      // (K[o0+4..7])
        const float4* pr =
            reinterpret_cast<const float4*>(Pt + i * PT_S + b_t * 8);
        const float4 pa = pr[0];
        const float4 pb = pr[1];
        const float pv[8] = {pa.x, pa.y, pa.z, pa.w, pb.x, pb.y, pb.z, pb.w};
        #pragma unroll
        for (int m = 0; m < 8; ++m) {
            const unsigned long long pp = pack2(pv[m], pv[m]);
            y[m][0] = fma2(ka.x,  pp, y[m][0]);
            y[m][1] = fma2(ka.y,  pp, y[m][1]);
            y[m][2] = fma2(kb2.x, pp, y[m][2]);
            y[m][3] = fma2(kb2.y, pp, y[m][3]);
        }
    }

    // ---- epilogue: partial[m] = sum over this thread's 8 o of y * q, then
    // shuffle-reduce across the 8 o-threads sharing each b row.
    #pragma unroll
    for (int m = 0; m < 8; ++m) {
        const int b = b0 + b_t * 8 + m;
        const ulonglong2* q2 =
            reinterpret_cast<const ulonglong2*>(x + (b * NF + c) * D + o_t * 8);
        const ulonglong2 qa = q2[0];
        const ulonglong2 qb = q2[1];
        unsigned long long acc = fma2(y[m][0], qa.x, 0ULL);
        acc = fma2(y[m][1], qa.y, acc);
        acc = fma2(y[m][2], qb.x, acc);
        acc = fma2(y[m][3], qb.y, acc);
        const float2 a = unpack2(acc);
        float partial = a.x + a.y;
        partial += __shfl_xor_sync(0xffffffffu, partial, 1);
        partial += __shfl_xor_sync(0xffffffffu, partial, 2);
        partial += __shfl_xor_sync(0xffffffffu, partial, 4);
        if (o_t == 0) out[b * NPAIR + n] = partial;
    }
}

extern "C" void kernel_launch(void* const* d_in, const int* in_sizes, int n_in,
                              void* d_out, int out_size) {
    (void)in_sizes; (void)n_in; (void)out_size;
    const float* x    = (const float*)d_in[0];
    const float* kern = (const float*)d_in[1];
    float* out        = (float*)d_out;

    dim3 grid(BATCH / BTILE, NPAIR, 1);
    opn_tile_kernel<<<grid, NTHR>>>(x, kern, out);
}